// round 12
// baseline (speedup 1.0000x reference)
#include <cuda_runtime.h>
#include <cuda_fp16.h>
#include <mma.h>
#include <cstdint>

using namespace nvcuda;

#define D_MODEL 1024
#define BATCH   4
#define SEQ     4096
#define M_TOTAL (BATCH*SEQ)
#define NX      (M_TOTAL*D_MODEL)      // 16M
#define D2      (D_MODEL*D_MODEL)      // 1M

#define CHUNK  32
#define NCHUNK (SEQ/CHUNK)   // 128

// ---------------- scratch (__device__ globals, allocation-free rule)
__device__ __half g_xh[NX];            // x (half)
__device__ __half g_uh[NX];            // u (half) after GEMM1
__device__ __half g_w1h[D2];
__device__ __half g_w2h[D2];
__device__ float  g_buf[NX];           // v after GEMM2
__device__ float  g_C  [BATCH*NCHUNK*D_MODEL];
__device__ float  g_cin[BATCH*NCHUNK*D_MODEL];

// ---------------- helpers
__device__ __forceinline__ uint32_t smem_u32(const void* p) {
    uint32_t a;
    asm("{ .reg .u64 t; cvta.to.shared.u64 t, %1; cvt.u32.u64 %0, t; }" : "=r"(a) : "l"(p));
    return a;
}
#define CP_ASYNC16(smem_addr, gptr) \
    asm volatile("cp.async.cg.shared.global [%0], [%1], 16;" :: "r"(smem_addr), "l"(gptr))
#define CP_COMMIT() asm volatile("cp.async.commit_group;" ::: "memory")
#define CP_WAIT(n)  asm volatile("cp.async.wait_group %0;" :: "n"(n) : "memory")

// ---------------- f32 -> f16 conversion (vectorized)
__global__ __launch_bounds__(256) void to_half(const float4* __restrict__ src,
                                               __half2* __restrict__ dst, int n4)
{
    int i = blockIdx.x * blockDim.x + threadIdx.x;
    if (i >= n4) return;
    float4 v = src[i];
    dst[2*i + 0] = __floats2half2_rn(v.x, v.y);
    dst[2*i + 1] = __floats2half2_rn(v.z, v.w);
}

// ---------------- fp16 wmma GEMM, 4-stage cp.async pipeline
// acc[m,n] = sum_d A[m,d]*W[n,d]; then:
//   out_h != 0 : out_h[m,n] = half((acc + bias[n]) * mask[m])   (smem staging epilogue)
//   else       : out_f[m,n] = acc                               (direct fragment store)
#define BM 128
#define BN 128
#define BK 32
#define LDT_H 40                         // half stride (80B rows, 16B aligned)
#define TILE_H (128*LDT_H)               // halves per tile (5120) = 10240 B
#define STAGE_H (2*TILE_H)               // A + B
#define STAGES 4
#define SMEM_BYTES (STAGES*STAGE_H*2)    // 81920 B
#define LDC 136
#define KITERS (D_MODEL/BK)              // 32

extern __shared__ __half sm_h[];

__global__ __launch_bounds__(256, 2)
void gemm_h(const __half* __restrict__ A, const __half* __restrict__ W,
            const float* __restrict__ bias, const float* __restrict__ mask,
            __half* __restrict__ out_h, float* __restrict__ out_f)
{
    const int tid    = threadIdx.x;
    const int warp   = tid >> 5;
    const int warp_m = warp & 3;   // 4 row tiles of 32
    const int warp_n = warp >> 2;  // 2 col tiles of 64
    const int m0 = blockIdx.y * BM;
    const int n0 = blockIdx.x * BN;

    const uint32_t sbase = smem_u32(sm_h);

    // 128x32 halves per tile = 512 chunks of 8 halves; 256 threads -> 2 chunks/matrix.
    const int r_ld [2] = { (tid + 0)   >> 2, (tid + 256) >> 2 };
    const int c8_ld[2] = { ((tid + 0) & 3) << 3, ((tid + 256) & 3) << 3 };

    auto issue = [&](int ki, int buf) {
        const int k0 = ki * BK;
        const uint32_t sa = sbase + (uint32_t)(buf * STAGE_H) * 2u;
        const uint32_t sb = sa + TILE_H * 2u;
        #pragma unroll
        for (int j = 0; j < 2; j++) {
            int r = r_ld[j], c8 = c8_ld[j];
            uint32_t so = (uint32_t)(r * LDT_H + c8) * 2u;
            CP_ASYNC16(sa + so, A + (size_t)(m0 + r) * D_MODEL + k0 + c8);
            CP_ASYNC16(sb + so, W + (size_t)(n0 + r) * D_MODEL + k0 + c8);
        }
    };

    wmma::fragment<wmma::accumulator, 16, 16, 16, float> acc[2][4];
    #pragma unroll
    for (int i = 0; i < 2; i++)
        #pragma unroll
        for (int j = 0; j < 4; j++)
            wmma::fill_fragment(acc[i][j], 0.0f);

    #pragma unroll
    for (int s = 0; s < STAGES - 1; s++) { issue(s, s); CP_COMMIT(); }

    for (int i = 0; i < KITERS; i++) {
        CP_WAIT(STAGES - 2);
        __syncthreads();

        if (i + STAGES - 1 < KITERS) issue(i + STAGES - 1, (i + STAGES - 1) % STAGES);
        CP_COMMIT();

        const __half* As = sm_h + (i % STAGES) * STAGE_H;
        const __half* Bs = As + TILE_H;

        #pragma unroll
        for (int kk = 0; kk < BK; kk += 16) {
            wmma::fragment<wmma::matrix_a, 16, 16, 16, half, wmma::row_major> af[2];
            wmma::fragment<wmma::matrix_b, 16, 16, 16, half, wmma::col_major> bf[4];
            #pragma unroll
            for (int a = 0; a < 2; a++)
                wmma::load_matrix_sync(af[a], As + (warp_m * 32 + a * 16) * LDT_H + kk, LDT_H);
            #pragma unroll
            for (int b = 0; b < 4; b++)
                wmma::load_matrix_sync(bf[b], Bs + (warp_n * 64 + b * 16) * LDT_H + kk, LDT_H);
            #pragma unroll
            for (int a = 0; a < 2; a++)
                #pragma unroll
                for (int b = 0; b < 4; b++)
                    wmma::mma_sync(acc[a][b], af[a], bf[b], acc[a][b]);
        }
    }

    if (out_f) {
        // Direct fragment store to global (fp32, no bias/mask) — no smem roundtrip.
        #pragma unroll
        for (int a = 0; a < 2; a++)
            #pragma unroll
            for (int b = 0; b < 4; b++) {
                size_t o = (size_t)(m0 + warp_m * 32 + a * 16) * D_MODEL
                         + (n0 + warp_n * 64 + b * 16);
                wmma::store_matrix_sync(out_f + o, acc[a][b], D_MODEL, wmma::mem_row_major);
            }
        return;
    }

    __syncthreads();

    // Epilogue: two 64-row stages through smem; fuse bias+mask; half output.
    float* Cs = (float*)sm_h;
    #pragma unroll
    for (int stage = 0; stage < 2; stage++) {
        if ((warp_m >> 1) == stage) {
            int rbase = (warp_m & 1) * 32;
            #pragma unroll
            for (int a = 0; a < 2; a++)
                #pragma unroll
                for (int b = 0; b < 4; b++)
                    wmma::store_matrix_sync(Cs + (rbase + a * 16) * LDC + warp_n * 64 + b * 16,
                                            acc[a][b], LDC, wmma::mem_row_major);
        }
        __syncthreads();
        #pragma unroll
        for (int it = 0; it < 8; it++) {
            int idx = (tid + it * 256) << 2;   // 0..8188
            int rr = idx >> 7;                 // 0..63
            int cc = idx & 127;
            int gm = m0 + stage * 64 + rr;
            int gn = n0 + cc;
            float4 v = *(const float4*)(Cs + rr * LDC + cc);
            float4 bb = *(const float4*)(bias + gn);
            float mv = mask[gm];
            v.x = (v.x + bb.x) * mv;
            v.y = (v.y + bb.y) * mv;
            v.z = (v.z + bb.z) * mv;
            v.w = (v.w + bb.w) * mv;
            __half2* dst = (__half2*)(out_h + (size_t)gm * D_MODEL + gn);
            dst[0] = __floats2half2_rn(v.x, v.y);
            dst[1] = __floats2half2_rn(v.z, v.w);
        }
        __syncthreads();
    }
}

// ---------------- Decay scan on g_buf (h_t = decay*h_{t-1} + v_t), chunked 3-pass, float4
__device__ __forceinline__ float get_decay(const float* dp) {
    return 1.0f / (1.0f + expf(-dp[0]));
}

// One block = one (batch, chunk); 256 threads x float4 cover e = 0..1023.
__global__ __launch_bounds__(256) void scan_pass1(const float* __restrict__ dp)
{
    float decay = get_decay(dp);
    int c = blockIdx.x;
    int b = blockIdx.y;
    int e4 = threadIdx.x << 2;
    const float* u = g_buf + ((size_t)(b * SEQ + c * CHUNK)) * D_MODEL + e4;
    float4 h = make_float4(0.f, 0.f, 0.f, 0.f);
    #pragma unroll 8
    for (int s = 0; s < CHUNK; s++) {
        float4 v = *(const float4*)(u + (size_t)s * D_MODEL);
        h.x = fmaf(decay, h.x, v.x);
        h.y = fmaf(decay, h.y, v.y);
        h.z = fmaf(decay, h.z, v.z);
        h.w = fmaf(decay, h.w, v.w);
    }
    *(float4*)(g_C + ((size_t)b * NCHUNK + c) * D_MODEL + e4) = h;
}

__global__ __launch_bounds__(256) void scan_pass2(const float* __restrict__ dp)
{
    float decay = get_decay(dp);
    float dpow = decay;
    #pragma unroll
    for (int i = 0; i < 5; i++) dpow *= dpow;  // decay^32 (CHUNK=32)
    int idx = blockIdx.x * 256 + threadIdx.x;  // 0..4095
    int b = idx >> 10;
    int e = idx & 1023;
    float he = 0.0f;
    #pragma unroll 8
    for (int c = 0; c < NCHUNK; c++) {
        size_t off = ((size_t)b * NCHUNK + c) * D_MODEL + e;
        g_cin[off] = he;
        he = fmaf(dpow, he, g_C[off]);
    }
}

__global__ __launch_bounds__(256) void scan_pass3(const float* __restrict__ dp,
                                                  const float* __restrict__ bias,
                                                  float* __restrict__ dst)
{
    float decay = get_decay(dp);
    int c = blockIdx.x;
    int b = blockIdx.y;
    int e4 = threadIdx.x << 2;
    size_t base = ((size_t)(b * SEQ + c * CHUNK)) * D_MODEL + e4;
    const float* u = g_buf + base;
    float*       o = dst  + base;
    float4 bf = *(const float4*)(bias + e4);
    float4 acc = *(const float4*)(g_cin + ((size_t)b * NCHUNK + c) * D_MODEL + e4);
    #pragma unroll 8
    for (int s = 0; s < CHUNK; s++) {
        float4 v = *(const float4*)(u + (size_t)s * D_MODEL);
        acc.x = fmaf(decay, acc.x, v.x);
        acc.y = fmaf(decay, acc.y, v.y);
        acc.z = fmaf(decay, acc.z, v.z);
        acc.w = fmaf(decay, acc.w, v.w);
        float4 w;
        w.x = acc.x + bf.x;
        w.y = acc.y + bf.y;
        w.z = acc.z + bf.z;
        w.w = acc.w + bf.w;
        *(float4*)(o + (size_t)s * D_MODEL) = w;
    }
}

// ---------------- launch
extern "C" void kernel_launch(void* const* d_in, const int* in_sizes, int n_in,
                              void* d_out, int out_size)
{
    const float* x     = (const float*)d_in[0];
    const float* mask  = (const float*)d_in[1];
    const float* W_up  = (const float*)d_in[2];
    const float* b_up  = (const float*)d_in[3];
    const float* W_f   = (const float*)d_in[4];
    const float* b_f   = (const float*)d_in[5];
    const float* dp    = (const float*)d_in[6];
    float* out = (float*)d_out;

    __half *xh, *uh, *w1h, *w2h;
    float* buf;
    cudaGetSymbolAddress((void**)&xh,  g_xh);
    cudaGetSymbolAddress((void**)&uh,  g_uh);
    cudaGetSymbolAddress((void**)&w1h, g_w1h);
    cudaGetSymbolAddress((void**)&w2h, g_w2h);
    cudaGetSymbolAddress((void**)&buf, g_buf);

    cudaFuncSetAttribute(gemm_h, cudaFuncAttributeMaxDynamicSharedMemorySize, SMEM_BYTES);

    dim3 ggrid(D_MODEL / BN, M_TOTAL / BM);   // (8, 128)

    // convert inputs to fp16
    to_half<<<NX / 4 / 256, 256>>>((const float4*)x,    (__half2*)xh,  NX / 4);
    to_half<<<D2 / 4 / 256, 256>>>((const float4*)W_up, (__half2*)w1h, D2 / 4);
    to_half<<<D2 / 4 / 256, 256>>>((const float4*)W_f,  (__half2*)w2h, D2 / 4);

    // u = half((x @ W_up^T + b_up) * mask)
    gemm_h<<<ggrid, 256, SMEM_BYTES>>>(xh, w1h, b_up, mask, uh, nullptr);

    // v = u @ W_f^T  (fp32 out; scan commutes with the linear map)
    gemm_h<<<ggrid, 256, SMEM_BYTES>>>(uh, w2h, nullptr, nullptr, nullptr, buf);

    // out = scan(v) + b_f
    scan_pass1<<<dim3(NCHUNK, BATCH), 256>>>(dp);
    scan_pass2<<<16, 256>>>(dp);
    scan_pass3<<<dim3(NCHUNK, BATCH), 256>>>(dp, b_f, out);
}

// round 14
// speedup vs baseline: 1.0304x; 1.0304x over previous
#include <cuda_runtime.h>
#include <cuda_fp16.h>
#include <mma.h>
#include <cstdint>

using namespace nvcuda;

#define D_MODEL 1024
#define BATCH   4
#define SEQ     4096
#define M_TOTAL (BATCH*SEQ)
#define NX      (M_TOTAL*D_MODEL)      // 16M
#define D2      (D_MODEL*D_MODEL)      // 1M

#define CHUNK  32
#define NCHUNK (SEQ/CHUNK)   // 128

// ---------------- scratch (__device__ globals, allocation-free rule)
__device__ __half g_xh[NX];            // x (half); reused as v (half) after GEMM2
__device__ __half g_uh[NX];            // u (half) after GEMM1
__device__ __half g_w1h[D2];
__device__ __half g_w2h[D2];
__device__ float  g_C  [BATCH*NCHUNK*D_MODEL];
__device__ float  g_cin[BATCH*NCHUNK*D_MODEL];

// ---------------- helpers
__device__ __forceinline__ uint32_t smem_u32(const void* p) {
    uint32_t a;
    asm("{ .reg .u64 t; cvta.to.shared.u64 t, %1; cvt.u32.u64 %0, t; }" : "=r"(a) : "l"(p));
    return a;
}
#define CP_ASYNC16(smem_addr, gptr) \
    asm volatile("cp.async.cg.shared.global [%0], [%1], 16;" :: "r"(smem_addr), "l"(gptr))
#define CP_COMMIT() asm volatile("cp.async.commit_group;" ::: "memory")
#define CP_WAIT(n)  asm volatile("cp.async.wait_group %0;" :: "n"(n) : "memory")

// ---------------- f32 -> f16 conversion (vectorized)
__global__ __launch_bounds__(256) void to_half(const float4* __restrict__ src,
                                               __half2* __restrict__ dst, int n4)
{
    int i = blockIdx.x * blockDim.x + threadIdx.x;
    if (i >= n4) return;
    float4 v = src[i];
    dst[2*i + 0] = __floats2half2_rn(v.x, v.y);
    dst[2*i + 1] = __floats2half2_rn(v.z, v.w);
}

// ---------------- fp16 wmma GEMM, 3-stage cp.async pipeline (R10 measured-best config)
// acc[m,n] = sum_d A[m,d]*W[n,d]
// out_h[m,n] = half( bias ? (acc + bias[n]) * mask[m] : acc )
#define BM 128
#define BN 128
#define BK 32
#define LDT_H 40                         // half stride (80B rows, 16B aligned)
#define TILE_H (128*LDT_H)               // halves per tile (5120) = 10240 B
#define STAGE_H (2*TILE_H)               // A + B
#define STAGES 3
#define SMEM_BYTES (STAGES*STAGE_H*2)    // 61440 B
#define LDC 136
#define KITERS (D_MODEL/BK)              // 32

extern __shared__ __half sm_h[];

__global__ __launch_bounds__(256, 2)
void gemm_h(const __half* __restrict__ A, const __half* __restrict__ W,
            const float* __restrict__ bias, const float* __restrict__ mask,
            __half* __restrict__ out_h)
{
    const int tid    = threadIdx.x;
    const int warp   = tid >> 5;
    const int warp_m = warp & 3;   // 4 row tiles of 32
    const int warp_n = warp >> 2;  // 2 col tiles of 64
    const int m0 = blockIdx.y * BM;
    const int n0 = blockIdx.x * BN;

    const uint32_t sbase = smem_u32(sm_h);

    // 128x32 halves per tile = 512 chunks of 8 halves; 256 threads -> 2 chunks/matrix.
    const int r_ld [2] = { (tid + 0)   >> 2, (tid + 256) >> 2 };
    const int c8_ld[2] = { ((tid + 0) & 3) << 3, ((tid + 256) & 3) << 3 };

    auto issue = [&](int ki, int buf) {
        const int k0 = ki * BK;
        const uint32_t sa = sbase + (uint32_t)(buf * STAGE_H) * 2u;
        const uint32_t sb = sa + TILE_H * 2u;
        #pragma unroll
        for (int j = 0; j < 2; j++) {
            int r = r_ld[j], c8 = c8_ld[j];
            uint32_t so = (uint32_t)(r * LDT_H + c8) * 2u;
            CP_ASYNC16(sa + so, A + (size_t)(m0 + r) * D_MODEL + k0 + c8);
            CP_ASYNC16(sb + so, W + (size_t)(n0 + r) * D_MODEL + k0 + c8);
        }
    };

    wmma::fragment<wmma::accumulator, 16, 16, 16, float> acc[2][4];
    #pragma unroll
    for (int i = 0; i < 2; i++)
        #pragma unroll
        for (int j = 0; j < 4; j++)
            wmma::fill_fragment(acc[i][j], 0.0f);

    #pragma unroll
    for (int s = 0; s < STAGES - 1; s++) { issue(s, s); CP_COMMIT(); }

    for (int i = 0; i < KITERS; i++) {
        CP_WAIT(1);
        __syncthreads();

        if (i + STAGES - 1 < KITERS) issue(i + STAGES - 1, (i + STAGES - 1) % STAGES);
        CP_COMMIT();

        const __half* As = sm_h + (i % STAGES) * STAGE_H;
        const __half* Bs = As + TILE_H;

        #pragma unroll
        for (int kk = 0; kk < BK; kk += 16) {
            wmma::fragment<wmma::matrix_a, 16, 16, 16, half, wmma::row_major> af[2];
            wmma::fragment<wmma::matrix_b, 16, 16, 16, half, wmma::col_major> bf[4];
            #pragma unroll
            for (int a = 0; a < 2; a++)
                wmma::load_matrix_sync(af[a], As + (warp_m * 32 + a * 16) * LDT_H + kk, LDT_H);
            #pragma unroll
            for (int b = 0; b < 4; b++)
                wmma::load_matrix_sync(bf[b], Bs + (warp_n * 64 + b * 16) * LDT_H + kk, LDT_H);
            #pragma unroll
            for (int a = 0; a < 2; a++)
                #pragma unroll
                for (int b = 0; b < 4; b++)
                    wmma::mma_sync(acc[a][b], af[a], bf[b], acc[a][b]);
        }
    }
    __syncthreads();

    // Epilogue: two 64-row stages through smem; fuse (optional) bias+mask; half output.
    float* Cs = (float*)sm_h;
    #pragma unroll
    for (int stage = 0; stage < 2; stage++) {
        if ((warp_m >> 1) == stage) {
            int rbase = (warp_m & 1) * 32;
            #pragma unroll
            for (int a = 0; a < 2; a++)
                #pragma unroll
                for (int b = 0; b < 4; b++)
                    wmma::store_matrix_sync(Cs + (rbase + a * 16) * LDC + warp_n * 64 + b * 16,
                                            acc[a][b], LDC, wmma::mem_row_major);
        }
        __syncthreads();
        #pragma unroll
        for (int it = 0; it < 8; it++) {
            int idx = (tid + it * 256) << 2;   // 0..8188
            int rr = idx >> 7;                 // 0..63
            int cc = idx & 127;
            int gm = m0 + stage * 64 + rr;
            int gn = n0 + cc;
            float4 v = *(const float4*)(Cs + rr * LDC + cc);
            if (bias) {
                float4 bb = *(const float4*)(bias + gn);
                float mv = mask[gm];
                v.x = (v.x + bb.x) * mv;
                v.y = (v.y + bb.y) * mv;
                v.z = (v.z + bb.z) * mv;
                v.w = (v.w + bb.w) * mv;
            }
            __half2* dst = (__half2*)(out_h + (size_t)gm * D_MODEL + gn);
            dst[0] = __floats2half2_rn(v.x, v.y);
            dst[1] = __floats2half2_rn(v.z, v.w);
        }
        __syncthreads();
    }
}

// ---------------- Decay scan on v (half), chunked 3-pass, 4 lanes/thread
__device__ __forceinline__ float get_decay(const float* dp) {
    return 1.0f / (1.0f + expf(-dp[0]));
}

// One block = one (batch, chunk); 256 threads x 4 half-lanes cover e = 0..1023.
__global__ __launch_bounds__(256) void scan_pass1(const float* __restrict__ dp)
{
    float decay = get_decay(dp);
    int c = blockIdx.x;
    int b = blockIdx.y;
    int e4 = threadIdx.x << 2;
    const __half* v = g_xh + ((size_t)(b * SEQ + c * CHUNK)) * D_MODEL + e4;
    float4 h = make_float4(0.f, 0.f, 0.f, 0.f);
    #pragma unroll 8
    for (int s = 0; s < CHUNK; s++) {
        uint2 raw = *(const uint2*)(v + (size_t)s * D_MODEL);
        float2 f0 = __half22float2(*(__half2*)&raw.x);
        float2 f1 = __half22float2(*(__half2*)&raw.y);
        h.x = fmaf(decay, h.x, f0.x);
        h.y = fmaf(decay, h.y, f0.y);
        h.z = fmaf(decay, h.z, f1.x);
        h.w = fmaf(decay, h.w, f1.y);
    }
    *(float4*)(g_C + ((size_t)b * NCHUNK + c) * D_MODEL + e4) = h;
}

__global__ __launch_bounds__(256) void scan_pass2(const float* __restrict__ dp)
{
    float decay = get_decay(dp);
    float dpow = decay;
    #pragma unroll
    for (int i = 0; i < 5; i++) dpow *= dpow;  // decay^32 (CHUNK=32)
    int idx = blockIdx.x * 256 + threadIdx.x;  // 0..4095
    int b = idx >> 10;
    int e = idx & 1023;
    float he = 0.0f;
    #pragma unroll 8
    for (int c = 0; c < NCHUNK; c++) {
        size_t off = ((size_t)b * NCHUNK + c) * D_MODEL + e;
        g_cin[off] = he;
        he = fmaf(dpow, he, g_C[off]);
    }
}

__global__ __launch_bounds__(256) void scan_pass3(const float* __restrict__ dp,
                                                  const float* __restrict__ bias,
                                                  float* __restrict__ dst)
{
    float decay = get_decay(dp);
    int c = blockIdx.x;
    int b = blockIdx.y;
    int e4 = threadIdx.x << 2;
    size_t base = ((size_t)(b * SEQ + c * CHUNK)) * D_MODEL + e4;
    const __half* v = g_xh + base;
    float*        o = dst  + base;
    float4 bf = *(const float4*)(bias + e4);
    float4 acc = *(const float4*)(g_cin + ((size_t)b * NCHUNK + c) * D_MODEL + e4);
    #pragma unroll 8
    for (int s = 0; s < CHUNK; s++) {
        uint2 raw = *(const uint2*)(v + (size_t)s * D_MODEL);
        float2 f0 = __half22float2(*(__half2*)&raw.x);
        float2 f1 = __half22float2(*(__half2*)&raw.y);
        acc.x = fmaf(decay, acc.x, f0.x);
        acc.y = fmaf(decay, acc.y, f0.y);
        acc.z = fmaf(decay, acc.z, f1.x);
        acc.w = fmaf(decay, acc.w, f1.y);
        float4 w;
        w.x = acc.x + bf.x;
        w.y = acc.y + bf.y;
        w.z = acc.z + bf.z;
        w.w = acc.w + bf.w;
        *(float4*)(o + (size_t)s * D_MODEL) = w;
    }
}

// ---------------- launch
extern "C" void kernel_launch(void* const* d_in, const int* in_sizes, int n_in,
                              void* d_out, int out_size)
{
    const float* x     = (const float*)d_in[0];
    const float* mask  = (const float*)d_in[1];
    const float* W_up  = (const float*)d_in[2];
    const float* b_up  = (const float*)d_in[3];
    const float* W_f   = (const float*)d_in[4];
    const float* b_f   = (const float*)d_in[5];
    const float* dp    = (const float*)d_in[6];
    float* out = (float*)d_out;

    __half *xh, *uh, *w1h, *w2h;
    cudaGetSymbolAddress((void**)&xh,  g_xh);
    cudaGetSymbolAddress((void**)&uh,  g_uh);
    cudaGetSymbolAddress((void**)&w1h, g_w1h);
    cudaGetSymbolAddress((void**)&w2h, g_w2h);

    cudaFuncSetAttribute(gemm_h, cudaFuncAttributeMaxDynamicSharedMemorySize, SMEM_BYTES);

    dim3 ggrid(D_MODEL / BN, M_TOTAL / BM);   // (8, 128)

    // convert inputs to fp16
    to_half<<<NX / 4 / 256, 256>>>((const float4*)x,    (__half2*)xh,  NX / 4);
    to_half<<<D2 / 4 / 256, 256>>>((const float4*)W_up, (__half2*)w1h, D2 / 4);
    to_half<<<D2 / 4 / 256, 256>>>((const float4*)W_f,  (__half2*)w2h, D2 / 4);

    // u = half((x @ W_up^T + b_up) * mask)
    gemm_h<<<ggrid, 256, SMEM_BYTES>>>(xh, w1h, b_up, mask, uh);

    // v = half(u @ W_f^T)   (x dead -> reuse g_xh as v; scan commutes with linear map)
    gemm_h<<<ggrid, 256, SMEM_BYTES>>>(uh, w2h, nullptr, nullptr, xh);

    // out = scan(v) + b_f
    scan_pass1<<<dim3(NCHUNK, BATCH), 256>>>(dp);
    scan_pass2<<<16, 256>>>(dp);
    scan_pass3<<<dim3(NCHUNK, BATCH), 256>>>(dp, b_f, out);
}